// round 15
// baseline (speedup 1.0000x reference)
#include <cuda_runtime.h>
#include <math.h>
#include <cstdint>

#define HEADS 8
#define HD 32
#define NPOS 2304
#define GW 48
#define CDIM 256
#define BATCH 2
#define MTOT (BATCH*NPOS)   // 4608
#define BH (BATCH*HEADS)    // 16

// Scratch (static device arrays; no allocation allowed)
__device__ float g_v[BATCH*HEADS*NPOS*HD];    // [bh][n][d] fp32 (dwconv, vt source)
__device__ float g_q[BATCH*HEADS*NPOS*HD];    // [bh][n][d] rotary q, tf32-rounded
__device__ float g_k[BATCH*HEADS*NPOS*HD];    // [bh][n][d] rotary scaled k, tf32-rounded
__device__ float g_vt[BATCH*HEADS*HD*NPOS];   // [bh][d][n] V transposed, tf32-rounded
__device__ float g_lepe[BATCH*NPOS*CDIM];
__device__ float g_wt[25*CDIM];
__device__ float g_sin[NPOS*16];
__device__ float g_cos[NPOS*16];
// split-K partials (unnormalized O and l)
__device__ float g_part[2*BH*NPOS*HD];
__device__ float g_partl[2*BH*NPOS];

// ---- tf32 helpers ----------------------------------------------------------
__device__ __forceinline__ uint32_t to_tf32(float f)
{
    uint32_t r;
    asm("cvt.rna.tf32.f32 %0, %1;" : "=r"(r) : "f"(f));
    return r;
}
__device__ __forceinline__ float to_tf32f(float f)
{
    return __uint_as_float(to_tf32(f));
}
__device__ __forceinline__ void mma_tf32(
    float* d, const uint32_t* a, uint32_t b0, uint32_t b1, const float* c)
{
    asm volatile(
        "mma.sync.aligned.m16n8k8.row.col.f32.tf32.tf32.f32 "
        "{%0,%1,%2,%3}, {%4,%5,%6,%7}, {%8,%9}, {%10,%11,%12,%13};"
        : "=f"(d[0]), "=f"(d[1]), "=f"(d[2]), "=f"(d[3])
        : "r"(a[0]), "r"(a[1]), "r"(a[2]), "r"(a[3]),
          "r"(b0), "r"(b1),
          "f"(c[0]), "f"(c[1]), "f"(c[2]), "f"(c[3]));
}
__device__ __forceinline__ uint32_t smem_u32(const void* p)
{
    uint32_t a;
    asm("{ .reg .u64 t; cvta.to.shared.u64 t, %1; cvt.u32.u64 %0, t; }" : "=r"(a) : "l"(p));
    return a;
}
__device__ __forceinline__ void cpa16(uint32_t saddr, const void* g)
{
    asm volatile("cp.async.cg.shared.global [%0], [%1], 16;" :: "r"(saddr), "l"(g));
}

// ---------------------------------------------------------------------------
// Setup: rotary sin/cos table + depthwise weight transpose (one kernel)
// ---------------------------------------------------------------------------
__global__ void setup_tables(const float* __restrict__ lw)
{
    int t = blockIdx.x * 256 + threadIdx.x;
    if (t < NPOS * 16) {
        int pos = t >> 4, pj = t & 15;
        float ang = expf(-(float)pj * (9.210340371976184f / 15.0f));
        float s, c;
        sincosf((float)pos * ang, &s, &c);
        g_sin[t] = s;
        g_cos[t] = c;
    } else {
        int u = t - NPOS * 16;
        if (u < 25 * CDIM) {
            int ch = u / 25, tap = u - ch * 25;
            g_wt[tap * CDIM + ch] = lw[u];
        }
    }
}

// ---------------------------------------------------------------------------
// tf32-mma QKV GEMM: y = x @ W + b; 128 threads, BM=128, BN=64, BK=32.
// grid (MTOT/128, CDIM/64, 3)
// ---------------------------------------------------------------------------
#define XS 36
#define WS 72

__global__ __launch_bounds__(128) void qkv_mma(
    const float* __restrict__ x,
    const float* __restrict__ Wq, const float* __restrict__ bq,
    const float* __restrict__ Wk, const float* __restrict__ bk,
    const float* __restrict__ Wv, const float* __restrict__ bv)
{
    const int which = blockIdx.z;
    const float* __restrict__ W    = (which == 0) ? Wq : (which == 1 ? Wk : Wv);
    const float* __restrict__ bias = (which == 0) ? bq : (which == 1 ? bk : bv);

    __shared__ __align__(16) float xs[128 * XS];
    __shared__ __align__(16) float ws[32 * WS];

    const int tid = threadIdx.x;
    const int lane = tid & 31, wid = tid >> 5;
    const int grp = lane >> 2, t4 = lane & 3;
    const int mb = blockIdx.x * 128, nb = blockIdx.y * 64;

    float acc[2][8][4];
#pragma unroll
    for (int mi = 0; mi < 2; mi++)
#pragma unroll
        for (int n = 0; n < 8; n++)
#pragma unroll
            for (int j = 0; j < 4; j++) acc[mi][n][j] = 0.f;

    for (int k0 = 0; k0 < CDIM; k0 += 32) {
        __syncthreads();
#pragma unroll
        for (int i = 0; i < 8; i++) {
            int idx = tid + i * 128;
            int row = idx >> 3, c = idx & 7;
            float4 a = *(const float4*)&x[(size_t)(mb + row) * CDIM + k0 + c * 4];
            a.x = to_tf32f(a.x); a.y = to_tf32f(a.y);
            a.z = to_tf32f(a.z); a.w = to_tf32f(a.w);
            *(float4*)(xs + row * XS + c * 4) = a;
        }
#pragma unroll
        for (int i = 0; i < 4; i++) {
            int idx = tid + i * 128;
            int row = idx >> 4, c = idx & 15;
            float4 a = *(const float4*)&W[(size_t)(k0 + row) * CDIM + nb + c * 4];
            a.x = to_tf32f(a.x); a.y = to_tf32f(a.y);
            a.z = to_tf32f(a.z); a.w = to_tf32f(a.w);
            *(float4*)(ws + row * WS + c * 4) = a;
        }
        __syncthreads();

#pragma unroll
        for (int ks = 0; ks < 4; ks++) {
            uint32_t bf[8][2];
#pragma unroll
            for (int n = 0; n < 8; n++) {
                bf[n][0] = __float_as_uint(ws[(ks * 8 + t4) * WS + n * 8 + grp]);
                bf[n][1] = __float_as_uint(ws[(ks * 8 + t4 + 4) * WS + n * 8 + grp]);
            }
            uint32_t af[2][4];
#pragma unroll
            for (int mi = 0; mi < 2; mi++) {
                const float* xrow = xs + (wid * 32 + mi * 16 + grp) * XS + ks * 8;
                const float* xrow8 = xrow + 8 * XS;
                af[mi][0] = __float_as_uint(xrow[t4]);
                af[mi][1] = __float_as_uint(xrow8[t4]);
                af[mi][2] = __float_as_uint(xrow[t4 + 4]);
                af[mi][3] = __float_as_uint(xrow8[t4 + 4]);
            }
#pragma unroll
            for (int mi = 0; mi < 2; mi++)
#pragma unroll
                for (int n = 0; n < 8; n++)
                    mma_tf32(acc[mi][n], af[mi], bf[n][0], bf[n][1], acc[mi][n]);
        }
    }

    const float scal = (which == 1) ? 0.17677669529663687f : 1.0f;

#pragma unroll
    for (int mi = 0; mi < 2; mi++) {
#pragma unroll
        for (int rh = 0; rh < 2; rh++) {
            int row = mb + wid * 32 + mi * 16 + rh * 8 + grp;
            int b = (row >= NPOS) ? 1 : 0;
            int pos = row - b * NPOS;
#pragma unroll
            for (int n = 0; n < 8; n++) {
                int col = nb + n * 8 + 2 * t4;
                float v0 = acc[mi][n][rh * 2 + 0] + bias[col];
                float v1 = acc[mi][n][rh * 2 + 1] + bias[col + 1];
                size_t base = (((size_t)(b * HEADS + (col >> 5))) * NPOS + pos) * HD + (col & 31);
                if (which == 2) {
                    *(float2*)&g_v[base] = make_float2(v0, v1);
                } else {
                    int pj = (col & 31) >> 1;
                    float s = g_sin[pos * 16 + pj];
                    float c = g_cos[pos * 16 + pj];
                    v0 *= scal; v1 *= scal;
                    float* dst = (which == 0) ? g_q : g_k;
                    *(float2*)&dst[base] =
                        make_float2(to_tf32f(v0 * c - v1 * s), to_tf32f(v1 * c + v0 * s));
                }
            }
        }
    }
}

// ---------------------------------------------------------------------------
// Transpose V: [bh][n][d] fp32 -> [bh][d][n] tf32-rounded fp32
// ---------------------------------------------------------------------------
__global__ __launch_bounds__(256) void vt_kernel()
{
    __shared__ float tile[32][33];
    const int bh = blockIdx.y;
    const int p0 = blockIdx.x * 32;
    const int tx = threadIdx.x, ty = threadIdx.y;
#pragma unroll
    for (int i = 0; i < 4; i++) {
        int row = ty + i * 8;
        tile[row][tx] = g_v[((size_t)bh * NPOS + p0 + row) * HD + tx];
    }
    __syncthreads();
#pragma unroll
    for (int i = 0; i < 4; i++) {
        int d = ty + i * 8;
        g_vt[((size_t)bh * HD + d) * NPOS + p0 + tx] = to_tf32f(tile[tx][d]);
    }
}

// ---------------------------------------------------------------------------
// Depthwise 5x5 conv, 4 outputs/thread.
// ---------------------------------------------------------------------------
__global__ __launch_bounds__(256) void dwconv(const float* __restrict__ lepe_b)
{
    int t = blockIdx.x * 256 + threadIdx.x;
    int ch = t & 255;
    int sp = t >> 8;
    int b = sp / 576;
    int rem = sp - b * 576;
    int rg = rem / 48;
    int c = rem - rg * 48;
    int r0 = rg * 4;

    const float* vb = g_v + ((size_t)(b * HEADS + (ch >> 5)) * NPOS) * HD + (ch & 31);

    float w[25];
#pragma unroll
    for (int i = 0; i < 25; i++) w[i] = g_wt[i * CDIM + ch];

    float bsv = lepe_b[ch];
    float s[4] = {bsv, bsv, bsv, bsv};

#pragma unroll
    for (int dri = 0; dri < 8; dri++) {
        const int dr = dri - 2;
        int rr = r0 + dr;
        if ((unsigned)rr < GW) {
            float vin[5];
#pragma unroll
            for (int jj = 0; jj < 5; jj++) {
                int cc = c + jj - 2;
                vin[jj] = ((unsigned)cc < GW) ? vb[(size_t)(rr * GW + cc) * HD] : 0.f;
            }
            const int jlo = (dr - 2 > 0) ? dr - 2 : 0;
            const int jhi = (dr + 2 < 3) ? dr + 2 : 3;
#pragma unroll
            for (int j = jlo; j <= jhi; j++) {
                const int wi = (dr - j + 2) * 5;
                s[j] += vin[0] * w[wi + 0] + vin[1] * w[wi + 1] + vin[2] * w[wi + 2]
                      + vin[3] * w[wi + 3] + vin[4] * w[wi + 4];
            }
        }
    }

#pragma unroll
    for (int j = 0; j < 4; j++) {
        g_lepe[((size_t)(b * NPOS + (r0 + j) * GW + c)) * CDIM + ch] = s[j];
    }
}

// ---------------------------------------------------------------------------
// Flash attention: tf32 mma, shuffle-free, 256 threads, 256 queries/block,
// 32 rows/warp, split-K over 2 key-halves, cp.async double buffer,
// software-pipelined group loop (QK of gr+1 overlaps exp/PV of gr).
// grid (NPOS/256 = 9, BH, 2).
// ---------------------------------------------------------------------------
#define KS_F 36
#define VT_F 132
#define ABUF 9088
#define AOFF_VT 4608
#define AOFF_KR 8832
#define AOFF_KC 8960
#define NTILE 9

__global__ __launch_bounds__(256) void attn_pipe()
{
    extern __shared__ __align__(16) float dyn[];
    const uint32_t sbase = smem_u32(dyn);

    const int tid = threadIdx.x;
    const int lane = tid & 31, wid = tid >> 5;
    const int grp = lane >> 2, t4 = lane & 3;
    const int sg = (grp >> 1) + ((grp & 1) << 2);   // sigma(grp)
    const int bh = blockIdx.y, h = bh & 7;
    const int half = blockIdx.z;
    const int q0 = blockIdx.x * 256;
    const int rowA = q0 + wid * 32 + grp;

    uint32_t qA[2][4][4];
    {
        const float* qb = g_q + (size_t)bh * NPOS * HD;
#pragma unroll
        for (int mi = 0; mi < 2; mi++)
#pragma unroll
            for (int s = 0; s < 4; s++) {
                const float* r0p = qb + (size_t)(rowA + mi * 16) * HD + s * 8;
                const float* r8p = r0p + 8 * HD;
                qA[mi][s][0] = __float_as_uint(r0p[t4]);
                qA[mi][s][1] = __float_as_uint(r8p[t4]);
                qA[mi][s][2] = __float_as_uint(r0p[t4 + 4]);
                qA[mi][s][3] = __float_as_uint(r8p[t4 + 4]);
            }
    }

    float o[2][4][4];
#pragma unroll
    for (int mi = 0; mi < 2; mi++)
#pragma unroll
        for (int i = 0; i < 4; i++)
#pragma unroll
            for (int j = 0; j < 4; j++) o[mi][i][j] = 0.f;
    float lA[2] = {0.f, 0.f}, lB[2] = {0.f, 0.f};

    float qrF[2][2], qcF[2][2];
#pragma unroll
    for (int mi = 0; mi < 2; mi++)
#pragma unroll
        for (int rh = 0; rh < 2; rh++) {
            int qr_ = rowA + mi * 16 + rh * 8;
            int qri = qr_ / GW;
            qrF[mi][rh] = (float)qri;
            qcF[mi][rh] = (float)(qr_ - qri * GW);
        }
    const float decay = logf(1.0f - exp2f(-(1.0f + 0.375f * (float)h)));

    const float* kb = g_k + (size_t)bh * NPOS * HD;
    const float* vtb = g_vt + (size_t)bh * HD * NPOS;

    auto fill = [&](int t, int bb) {
        const uint32_t bu = sbase + (uint32_t)bb * (ABUF * 4);
#pragma unroll
        for (int i = 0; i < 4; i++) {
            int idx = tid + i * 256;
            int row = idx >> 3, c = idx & 7;
            cpa16(bu + (uint32_t)(row * KS_F + c * 4) * 4,
                  kb + ((size_t)t * 128 + row) * HD + c * 4);
        }
#pragma unroll
        for (int i = 0; i < 4; i++) {
            int idx = tid + i * 256;
            int row = idx >> 5, c = idx & 31;
            cpa16(bu + (uint32_t)(AOFF_VT + row * VT_F + c * 4) * 4,
                  vtb + (size_t)row * NPOS + t * 128 + c * 4);
        }
        if (tid < 128) {
            int kk = t * 128 + tid;
            int kr = kk / GW;
            dyn[bb * ABUF + AOFF_KR + tid] = (float)kr;
            dyn[bb * ABUF + AOFF_KC + tid] = (float)(kk - kr * GW);
        }
        asm volatile("cp.async.commit_group;" ::: "memory");
    };

    const int t0 = half * NTILE;
    fill(t0, 0);

    for (int tt = 0; tt < NTILE; tt++) {
        const int bb = tt & 1;
        if (tt < NTILE - 1) {
            fill(t0 + tt + 1, bb ^ 1);
            asm volatile("cp.async.wait_group 1;" ::: "memory");
        } else {
            asm volatile("cp.async.wait_group 0;" ::: "memory");
        }
        __syncthreads();

        const float* ksS = dyn + bb * ABUF;
        const float* vtS = ksS + AOFF_VT;
        const float* krf = ksS + AOFF_KR;
        const float* kcf = ksS + AOFF_KC;

        // ---- pipelined group loop: QK of gr+1 overlaps exp/PV of gr ----
        float sfN[2][4];
        {
            const float* krow = ksS + sg * KS_F;
#pragma unroll
            for (int mi = 0; mi < 2; mi++)
                sfN[mi][0] = sfN[mi][1] = sfN[mi][2] = sfN[mi][3] = 0.f;
#pragma unroll
            for (int s = 0; s < 4; s++) {
                uint32_t b0 = __float_as_uint(krow[s * 8 + t4]);
                uint32_t b1 = __float_as_uint(krow[s * 8 + t4 + 4]);
                mma_tf32(sfN[0], qA[0][s], b0, b1, sfN[0]);
                mma_tf32(sfN[1], qA[1][s], b0, b1, sfN[1]);
            }
        }

#pragma unroll
        for (int gr = 0; gr < 16; gr++) {
            float sfC[2][4];
#pragma unroll
            for (int mi = 0; mi < 2; mi++)
#pragma unroll
                for (int j = 0; j < 4; j++) sfC[mi][j] = sfN[mi][j];

            if (gr < 15) {
                const float* krow = ksS + ((gr + 1) * 8 + sg) * KS_F;
#pragma unroll
                for (int mi = 0; mi < 2; mi++)
                    sfN[mi][0] = sfN[mi][1] = sfN[mi][2] = sfN[mi][3] = 0.f;
#pragma unroll
                for (int s = 0; s < 4; s++) {
                    uint32_t b0 = __float_as_uint(krow[s * 8 + t4]);
                    uint32_t b1 = __float_as_uint(krow[s * 8 + t4 + 4]);
                    mma_tf32(sfN[0], qA[0][s], b0, b1, sfN[0]);
                    mma_tf32(sfN[1], qA[1][s], b0, b1, sfN[1]);
                }
            }

            int col0 = gr * 8 + t4;
            int col1 = col0 + 4;
            float kra = krf[col0], kca = kcf[col0];
            float krb = krf[col1], kcb = kcf[col1];

            uint32_t aP[2][4];
#pragma unroll
            for (int mi = 0; mi < 2; mi++) {
                float p0 = to_tf32f(__expf(fmaf(decay,
                    fabsf(qrF[mi][0] - kra) + fabsf(qcF[mi][0] - kca), sfC[mi][0])));
                float p1 = to_tf32f(__expf(fmaf(decay,
                    fabsf(qrF[mi][0] - krb) + fabsf(qcF[mi][0] - kcb), sfC[mi][1])));
                float p2 = to_tf32f(__expf(fmaf(decay,
                    fabsf(qrF[mi][1] - kra) + fabsf(qcF[mi][1] - kca), sfC[mi][2])));
                float p3 = to_tf32f(__expf(fmaf(decay,
                    fabsf(qrF[mi][1] - krb) + fabsf(qcF[mi][1] - kcb), sfC[mi][3])));
                lA[mi] += p0 + p1;
                lB[mi] += p2 + p3;
                aP[mi][0] = __float_as_uint(p0);
                aP[mi][1] = __float_as_uint(p2);
                aP[mi][2] = __float_as_uint(p1);
                aP[mi][3] = __float_as_uint(p3);
            }

#pragma unroll
            for (int nc = 0; nc < 4; nc++) {
                const float* vrow = vtS + (nc * 8 + grp) * VT_F + gr * 8;
                uint32_t b0 = __float_as_uint(vrow[t4]);
                uint32_t b1 = __float_as_uint(vrow[t4 + 4]);
#pragma unroll
                for (int mi = 0; mi < 2; mi++)
                    mma_tf32(o[mi][nc], aP[mi], b0, b1, o[mi][nc]);
            }
        }
        __syncthreads();
    }

#pragma unroll
    for (int mi = 0; mi < 2; mi++) {
        lA[mi] += __shfl_xor_sync(0xFFFFFFFFu, lA[mi], 1);
        lA[mi] += __shfl_xor_sync(0xFFFFFFFFu, lA[mi], 2);
        lB[mi] += __shfl_xor_sync(0xFFFFFFFFu, lB[mi], 1);
        lB[mi] += __shfl_xor_sync(0xFFFFFFFFu, lB[mi], 2);
    }

    // store unnormalized partials
    float* pbase = g_part + (((size_t)(half * BH + bh)) * NPOS) * HD;
#pragma unroll
    for (int mi = 0; mi < 2; mi++) {
        const int r0 = rowA + mi * 16;
        float* p0 = pbase + (size_t)r0 * HD;
        float* p8 = pbase + (size_t)(r0 + 8) * HD;
#pragma unroll
        for (int nc = 0; nc < 4; nc++) {
            int d = nc * 8 + t4 * 2;
            *(float2*)(p0 + d) = make_float2(o[mi][nc][0], o[mi][nc][1]);
            *(float2*)(p8 + d) = make_float2(o[mi][nc][2], o[mi][nc][3]);
        }
        if (t4 == 0) {
            g_partl[(half * BH + bh) * NPOS + r0] = lA[mi];
            g_partl[(half * BH + bh) * NPOS + r0 + 8] = lB[mi];
        }
    }
}

// ---------------------------------------------------------------------------
// tf32-mma output GEMM with fused split-K merge:
// out = ((O0+O1)/(l0+l1) + lepe) @ Wo + bo
// A-tile built directly from g_part/g_partl/g_lepe. grid (MTOT/128, CDIM/64)
// ---------------------------------------------------------------------------
__global__ __launch_bounds__(128) void out_mma(
    const float* __restrict__ Wo, const float* __restrict__ bo,
    float* __restrict__ out)
{
    __shared__ __align__(16) float xs[128 * XS];
    __shared__ __align__(16) float ws[32 * WS];

    const int tid = threadIdx.x;
    const int lane = tid & 31, wid = tid >> 5;
    const int grp = lane >> 2, t4 = lane & 3;
    const int mb = blockIdx.x * 128, nb = blockIdx.y * 64;

    float acc[2][8][4];
#pragma unroll
    for (int mi = 0; mi < 2; mi++)
#pragma unroll
        for (int n = 0; n < 8; n++)
#pragma unroll
            for (int j = 0; j < 4; j++) acc[mi][n][j] = 0.f;

    for (int k0 = 0; k0 < CDIM; k0 += 32) {
        const int head = k0 >> 5;     // all cols in this chunk belong to one head
        __syncthreads();
#pragma unroll
        for (int i = 0; i < 8; i++) {
            int idx = tid + i * 128;
            int row = idx >> 3, c = idx & 7;
            int R = mb + row;
            int b = (R >= NPOS) ? 1 : 0;
            int pos = R - b * NPOS;
            int bhh = b * HEADS + head;
            float l0 = g_partl[bhh * NPOS + pos];
            float l1 = g_partl[(BH + bhh) * NPOS + pos];
            float inv = 1.0f / (l0 + l1);
            float4 a0 = *(const float4*)(g_part + ((size_t)bhh * NPOS + pos) * HD + c * 4);
            float4 a1 = *(const float4*)(g_part + ((size_t)(BH + bhh) * NPOS + pos) * HD + c * 4);
            float4 e = *(const float4*)&g_lepe[(size_t)R * CDIM + k0 + c * 4];
            float4 r;
            r.x = to_tf32f((a0.x + a1.x) * inv + e.x);
            r.y = to_tf32f((a0.y + a1.y) * inv + e.y);
            r.z = to_tf32f((a0.z + a1.z) * inv + e.z);
            r.w = to_tf32f((a0.w + a1.w) * inv + e.w);
            *(float4*)(xs + row * XS + c * 4) = r;
        }
#pragma unroll
        for (int i = 0; i < 4; i++) {
            int idx = tid + i * 128;
            int row = idx >> 4, c = idx & 15;
            float4 a = *(const float4*)&Wo[(size_t)(k0 + row) * CDIM + nb + c * 4];
            a.x = to_tf32f(a.x); a.y = to_tf32f(a.y);
            a.z = to_tf32f(a.z); a.w = to_tf32f(a.w);
            *(float4*)(ws + row * WS + c * 4) = a;
        }
        __syncthreads();

#pragma unroll
        for (int ks = 0; ks < 4; ks++) {
            uint32_t bf[8][2];
#pragma unroll
            for (int n = 0; n < 8; n++) {
                bf[n][0] = __float_as_uint(ws[(ks * 8 + t4) * WS + n * 8 + grp]);
                bf[n][1] = __float_as_uint(ws[(ks * 8 + t4 + 4) * WS + n * 8 + grp]);
            }
            uint32_t af[2][4];
#pragma unroll
            for (int mi = 0; mi < 2; mi++) {
                const float* xrow = xs + (wid * 32 + mi * 16 + grp) * XS + ks * 8;
                const float* xrow8 = xrow + 8 * XS;
                af[mi][0] = __float_as_uint(xrow[t4]);
                af[mi][1] = __float_as_uint(xrow8[t4]);
                af[mi][2] = __float_as_uint(xrow[t4 + 4]);
                af[mi][3] = __float_as_uint(xrow8[t4 + 4]);
            }
#pragma unroll
            for (int mi = 0; mi < 2; mi++)
#pragma unroll
                for (int n = 0; n < 8; n++)
                    mma_tf32(acc[mi][n], af[mi], bf[n][0], bf[n][1], acc[mi][n]);
        }
    }

#pragma unroll
    for (int mi = 0; mi < 2; mi++) {
#pragma unroll
        for (int rh = 0; rh < 2; rh++) {
            int row = mb + wid * 32 + mi * 16 + rh * 8 + grp;
#pragma unroll
            for (int n = 0; n < 8; n++) {
                int col = nb + n * 8 + 2 * t4;
                float v0 = acc[mi][n][rh * 2 + 0] + bo[col];
                float v1 = acc[mi][n][rh * 2 + 1] + bo[col + 1];
                *(float2*)&out[(size_t)row * CDIM + col] = make_float2(v0, v1);
            }
        }
    }
}

// ---------------------------------------------------------------------------
extern "C" void kernel_launch(void* const* d_in, const int* in_sizes, int n_in,
                              void* d_out, int out_size)
{
    const float* x      = (const float*)d_in[0];
    const float* Wq     = (const float*)d_in[1];
    const float* bq     = (const float*)d_in[2];
    const float* Wk     = (const float*)d_in[3];
    const float* bk     = (const float*)d_in[4];
    const float* Wv     = (const float*)d_in[5];
    const float* bv     = (const float*)d_in[6];
    const float* lepe_w = (const float*)d_in[7];
    const float* lepe_b = (const float*)d_in[8];
    const float* Wo     = (const float*)d_in[9];
    const float* bo     = (const float*)d_in[10];
    float* out = (float*)d_out;

    setup_tables<<<(NPOS * 16 + 25 * CDIM + 255) / 256, 256>>>(lepe_w);

    dim3 g1(MTOT / 128, CDIM / 64, 3);
    qkv_mma<<<g1, 128>>>(x, Wq, bq, Wk, bk, Wv, bv);

    dim3 gv(NPOS / 32, BH);
    vt_kernel<<<gv, dim3(32, 8)>>>();

    dwconv<<<(MTOT * CDIM / 4) / 256, 256>>>(lepe_b);

    const int attn_smem = 2 * ABUF * 4;   // 72704 B
    cudaFuncSetAttribute(attn_pipe, cudaFuncAttributeMaxDynamicSharedMemorySize, attn_smem);
    dim3 g3(NPOS / 256, BH, 2);
    attn_pipe<<<g3, 256, attn_smem>>>();

    dim3 g4(MTOT / 128, CDIM / 64);
    out_mma<<<g4, 128>>>(Wo, bo, out);
}

// round 16
// speedup vs baseline: 1.5067x; 1.5067x over previous
#include <cuda_runtime.h>
#include <math.h>
#include <cstdint>

#define HEADS 8
#define HD 32
#define NPOS 2304
#define GW 48
#define CDIM 256
#define BATCH 2
#define MTOT (BATCH*NPOS)   // 4608
#define BH (BATCH*HEADS)    // 16

// Scratch (static device arrays; no allocation allowed)
__device__ float g_v[BATCH*HEADS*NPOS*HD];    // [bh][n][d] fp32 (dwconv, vt source)
__device__ float g_q[BATCH*HEADS*NPOS*HD];    // [bh][n][d] rotary q, tf32-rounded
__device__ float g_k[BATCH*HEADS*NPOS*HD];    // [bh][n][d] rotary scaled k, tf32-rounded
__device__ float g_vt[BATCH*HEADS*HD*NPOS];   // [bh][d][n] V transposed, tf32-rounded
__device__ float g_lepe[BATCH*NPOS*CDIM];
__device__ float g_wt[25*CDIM];
__device__ float g_sin[NPOS*16];
__device__ float g_cos[NPOS*16];
// split-K partials (unnormalized O and l)
__device__ float g_part[2*BH*NPOS*HD];
__device__ float g_partl[2*BH*NPOS];

// ---- tf32 helpers ----------------------------------------------------------
__device__ __forceinline__ uint32_t to_tf32(float f)
{
    uint32_t r;
    asm("cvt.rna.tf32.f32 %0, %1;" : "=r"(r) : "f"(f));
    return r;
}
__device__ __forceinline__ float to_tf32f(float f)
{
    return __uint_as_float(to_tf32(f));
}
__device__ __forceinline__ void mma_tf32(
    float* d, const uint32_t* a, uint32_t b0, uint32_t b1, const float* c)
{
    asm volatile(
        "mma.sync.aligned.m16n8k8.row.col.f32.tf32.tf32.f32 "
        "{%0,%1,%2,%3}, {%4,%5,%6,%7}, {%8,%9}, {%10,%11,%12,%13};"
        : "=f"(d[0]), "=f"(d[1]), "=f"(d[2]), "=f"(d[3])
        : "r"(a[0]), "r"(a[1]), "r"(a[2]), "r"(a[3]),
          "r"(b0), "r"(b1),
          "f"(c[0]), "f"(c[1]), "f"(c[2]), "f"(c[3]));
}
__device__ __forceinline__ uint32_t smem_u32(const void* p)
{
    uint32_t a;
    asm("{ .reg .u64 t; cvta.to.shared.u64 t, %1; cvt.u32.u64 %0, t; }" : "=r"(a) : "l"(p));
    return a;
}
__device__ __forceinline__ void cpa16(uint32_t saddr, const void* g)
{
    asm volatile("cp.async.cg.shared.global [%0], [%1], 16;" :: "r"(saddr), "l"(g));
}

// ---------------------------------------------------------------------------
// Setup: rotary sin/cos table + depthwise weight transpose (one kernel)
// ---------------------------------------------------------------------------
__global__ void setup_tables(const float* __restrict__ lw)
{
    int t = blockIdx.x * 256 + threadIdx.x;
    if (t < NPOS * 16) {
        int pos = t >> 4, pj = t & 15;
        float ang = expf(-(float)pj * (9.210340371976184f / 15.0f));
        float s, c;
        sincosf((float)pos * ang, &s, &c);
        g_sin[t] = s;
        g_cos[t] = c;
    } else {
        int u = t - NPOS * 16;
        if (u < 25 * CDIM) {
            int ch = u / 25, tap = u - ch * 25;
            g_wt[tap * CDIM + ch] = lw[u];
        }
    }
}

// ---------------------------------------------------------------------------
// tf32-mma QKV GEMM: y = x @ W + b; 128 threads, BM=128, BN=64, BK=32.
// grid (MTOT/128, CDIM/64, 3)
// ---------------------------------------------------------------------------
#define XS 36
#define WS 72

__global__ __launch_bounds__(128) void qkv_mma(
    const float* __restrict__ x,
    const float* __restrict__ Wq, const float* __restrict__ bq,
    const float* __restrict__ Wk, const float* __restrict__ bk,
    const float* __restrict__ Wv, const float* __restrict__ bv)
{
    const int which = blockIdx.z;
    const float* __restrict__ W    = (which == 0) ? Wq : (which == 1 ? Wk : Wv);
    const float* __restrict__ bias = (which == 0) ? bq : (which == 1 ? bk : bv);

    __shared__ __align__(16) float xs[128 * XS];
    __shared__ __align__(16) float ws[32 * WS];

    const int tid = threadIdx.x;
    const int lane = tid & 31, wid = tid >> 5;
    const int grp = lane >> 2, t4 = lane & 3;
    const int mb = blockIdx.x * 128, nb = blockIdx.y * 64;

    float acc[2][8][4];
#pragma unroll
    for (int mi = 0; mi < 2; mi++)
#pragma unroll
        for (int n = 0; n < 8; n++)
#pragma unroll
            for (int j = 0; j < 4; j++) acc[mi][n][j] = 0.f;

    for (int k0 = 0; k0 < CDIM; k0 += 32) {
        __syncthreads();
#pragma unroll
        for (int i = 0; i < 8; i++) {
            int idx = tid + i * 128;
            int row = idx >> 3, c = idx & 7;
            float4 a = *(const float4*)&x[(size_t)(mb + row) * CDIM + k0 + c * 4];
            a.x = to_tf32f(a.x); a.y = to_tf32f(a.y);
            a.z = to_tf32f(a.z); a.w = to_tf32f(a.w);
            *(float4*)(xs + row * XS + c * 4) = a;
        }
#pragma unroll
        for (int i = 0; i < 4; i++) {
            int idx = tid + i * 128;
            int row = idx >> 4, c = idx & 15;
            float4 a = *(const float4*)&W[(size_t)(k0 + row) * CDIM + nb + c * 4];
            a.x = to_tf32f(a.x); a.y = to_tf32f(a.y);
            a.z = to_tf32f(a.z); a.w = to_tf32f(a.w);
            *(float4*)(ws + row * WS + c * 4) = a;
        }
        __syncthreads();

#pragma unroll
        for (int ks = 0; ks < 4; ks++) {
            uint32_t bf[8][2];
#pragma unroll
            for (int n = 0; n < 8; n++) {
                bf[n][0] = __float_as_uint(ws[(ks * 8 + t4) * WS + n * 8 + grp]);
                bf[n][1] = __float_as_uint(ws[(ks * 8 + t4 + 4) * WS + n * 8 + grp]);
            }
            uint32_t af[2][4];
#pragma unroll
            for (int mi = 0; mi < 2; mi++) {
                const float* xrow = xs + (wid * 32 + mi * 16 + grp) * XS + ks * 8;
                const float* xrow8 = xrow + 8 * XS;
                af[mi][0] = __float_as_uint(xrow[t4]);
                af[mi][1] = __float_as_uint(xrow8[t4]);
                af[mi][2] = __float_as_uint(xrow[t4 + 4]);
                af[mi][3] = __float_as_uint(xrow8[t4 + 4]);
            }
#pragma unroll
            for (int mi = 0; mi < 2; mi++)
#pragma unroll
                for (int n = 0; n < 8; n++)
                    mma_tf32(acc[mi][n], af[mi], bf[n][0], bf[n][1], acc[mi][n]);
        }
    }

    const float scal = (which == 1) ? 0.17677669529663687f : 1.0f;

#pragma unroll
    for (int mi = 0; mi < 2; mi++) {
#pragma unroll
        for (int rh = 0; rh < 2; rh++) {
            int row = mb + wid * 32 + mi * 16 + rh * 8 + grp;
            int b = (row >= NPOS) ? 1 : 0;
            int pos = row - b * NPOS;
#pragma unroll
            for (int n = 0; n < 8; n++) {
                int col = nb + n * 8 + 2 * t4;
                float v0 = acc[mi][n][rh * 2 + 0] + bias[col];
                float v1 = acc[mi][n][rh * 2 + 1] + bias[col + 1];
                size_t base = (((size_t)(b * HEADS + (col >> 5))) * NPOS + pos) * HD + (col & 31);
                if (which == 2) {
                    *(float2*)&g_v[base] = make_float2(v0, v1);
                } else {
                    int pj = (col & 31) >> 1;
                    float s = g_sin[pos * 16 + pj];
                    float c = g_cos[pos * 16 + pj];
                    v0 *= scal; v1 *= scal;
                    float* dst = (which == 0) ? g_q : g_k;
                    *(float2*)&dst[base] =
                        make_float2(to_tf32f(v0 * c - v1 * s), to_tf32f(v1 * c + v0 * s));
                }
            }
        }
    }
}

// ---------------------------------------------------------------------------
// Transpose V: [bh][n][d] fp32 -> [bh][d][n] tf32-rounded fp32
// ---------------------------------------------------------------------------
__global__ __launch_bounds__(256) void vt_kernel()
{
    __shared__ float tile[32][33];
    const int bh = blockIdx.y;
    const int p0 = blockIdx.x * 32;
    const int tx = threadIdx.x, ty = threadIdx.y;
#pragma unroll
    for (int i = 0; i < 4; i++) {
        int row = ty + i * 8;
        tile[row][tx] = g_v[((size_t)bh * NPOS + p0 + row) * HD + tx];
    }
    __syncthreads();
#pragma unroll
    for (int i = 0; i < 4; i++) {
        int d = ty + i * 8;
        g_vt[((size_t)bh * HD + d) * NPOS + p0 + tx] = to_tf32f(tile[tx][d]);
    }
}

// ---------------------------------------------------------------------------
// Depthwise 5x5 conv, 4 outputs/thread.
// ---------------------------------------------------------------------------
__global__ __launch_bounds__(256) void dwconv(const float* __restrict__ lepe_b)
{
    int t = blockIdx.x * 256 + threadIdx.x;
    int ch = t & 255;
    int sp = t >> 8;
    int b = sp / 576;
    int rem = sp - b * 576;
    int rg = rem / 48;
    int c = rem - rg * 48;
    int r0 = rg * 4;

    const float* vb = g_v + ((size_t)(b * HEADS + (ch >> 5)) * NPOS) * HD + (ch & 31);

    float w[25];
#pragma unroll
    for (int i = 0; i < 25; i++) w[i] = g_wt[i * CDIM + ch];

    float bsv = lepe_b[ch];
    float s[4] = {bsv, bsv, bsv, bsv};

#pragma unroll
    for (int dri = 0; dri < 8; dri++) {
        const int dr = dri - 2;
        int rr = r0 + dr;
        if ((unsigned)rr < GW) {
            float vin[5];
#pragma unroll
            for (int jj = 0; jj < 5; jj++) {
                int cc = c + jj - 2;
                vin[jj] = ((unsigned)cc < GW) ? vb[(size_t)(rr * GW + cc) * HD] : 0.f;
            }
            const int jlo = (dr - 2 > 0) ? dr - 2 : 0;
            const int jhi = (dr + 2 < 3) ? dr + 2 : 3;
#pragma unroll
            for (int j = jlo; j <= jhi; j++) {
                const int wi = (dr - j + 2) * 5;
                s[j] += vin[0] * w[wi + 0] + vin[1] * w[wi + 1] + vin[2] * w[wi + 2]
                      + vin[3] * w[wi + 3] + vin[4] * w[wi + 4];
            }
        }
    }

#pragma unroll
    for (int j = 0; j < 4; j++) {
        g_lepe[((size_t)(b * NPOS + (r0 + j) * GW + c)) * CDIM + ch] = s[j];
    }
}

// ---------------------------------------------------------------------------
// Flash attention: tf32 mma, shuffle-free, 256 threads, 256 queries/block,
// 32 rows/warp, split-K over 2 key-halves, double-buffered cp.async.
// (R14 configuration — NO software pipelining; that spilled registers.)
// grid (NPOS/256 = 9, BH, 2). Unnormalized partials (O, l) -> fused merge
// in out_mma.
// ---------------------------------------------------------------------------
#define KS_F 36
#define VT_F 132
#define ABUF 9088
#define AOFF_VT 4608
#define AOFF_KR 8832
#define AOFF_KC 8960
#define NTILE 9               // key tiles per half

__global__ __launch_bounds__(256) void attn_pipe()
{
    extern __shared__ __align__(16) float dyn[];
    const uint32_t sbase = smem_u32(dyn);

    const int tid = threadIdx.x;
    const int lane = tid & 31, wid = tid >> 5;
    const int grp = lane >> 2, t4 = lane & 3;
    const int sg = (grp >> 1) + ((grp & 1) << 2);   // sigma(grp)
    const int bh = blockIdx.y, h = bh & 7;
    const int half = blockIdx.z;
    const int q0 = blockIdx.x * 256;
    const int rowA = q0 + wid * 32 + grp;

    uint32_t qA[2][4][4];
    {
        const float* qb = g_q + (size_t)bh * NPOS * HD;
#pragma unroll
        for (int mi = 0; mi < 2; mi++)
#pragma unroll
            for (int s = 0; s < 4; s++) {
                const float* r0p = qb + (size_t)(rowA + mi * 16) * HD + s * 8;
                const float* r8p = r0p + 8 * HD;
                qA[mi][s][0] = __float_as_uint(r0p[t4]);
                qA[mi][s][1] = __float_as_uint(r8p[t4]);
                qA[mi][s][2] = __float_as_uint(r0p[t4 + 4]);
                qA[mi][s][3] = __float_as_uint(r8p[t4 + 4]);
            }
    }

    float o[2][4][4];
#pragma unroll
    for (int mi = 0; mi < 2; mi++)
#pragma unroll
        for (int i = 0; i < 4; i++)
#pragma unroll
            for (int j = 0; j < 4; j++) o[mi][i][j] = 0.f;
    float lA[2] = {0.f, 0.f}, lB[2] = {0.f, 0.f};

    float qrF[2][2], qcF[2][2];
#pragma unroll
    for (int mi = 0; mi < 2; mi++)
#pragma unroll
        for (int rh = 0; rh < 2; rh++) {
            int qr_ = rowA + mi * 16 + rh * 8;
            int qri = qr_ / GW;
            qrF[mi][rh] = (float)qri;
            qcF[mi][rh] = (float)(qr_ - qri * GW);
        }
    const float decay = logf(1.0f - exp2f(-(1.0f + 0.375f * (float)h)));

    const float* kb = g_k + (size_t)bh * NPOS * HD;
    const float* vtb = g_vt + (size_t)bh * HD * NPOS;

    auto fill = [&](int t, int bb) {
        const uint32_t bu = sbase + (uint32_t)bb * (ABUF * 4);
#pragma unroll
        for (int i = 0; i < 4; i++) {
            int idx = tid + i * 256;
            int row = idx >> 3, c = idx & 7;
            cpa16(bu + (uint32_t)(row * KS_F + c * 4) * 4,
                  kb + ((size_t)t * 128 + row) * HD + c * 4);
        }
#pragma unroll
        for (int i = 0; i < 4; i++) {
            int idx = tid + i * 256;
            int row = idx >> 5, c = idx & 31;
            cpa16(bu + (uint32_t)(AOFF_VT + row * VT_F + c * 4) * 4,
                  vtb + (size_t)row * NPOS + t * 128 + c * 4);
        }
        if (tid < 128) {
            int kk = t * 128 + tid;
            int kr = kk / GW;
            dyn[bb * ABUF + AOFF_KR + tid] = (float)kr;
            dyn[bb * ABUF + AOFF_KC + tid] = (float)(kk - kr * GW);
        }
        asm volatile("cp.async.commit_group;" ::: "memory");
    };

    const int t0 = half * NTILE;
    fill(t0, 0);

    for (int tt = 0; tt < NTILE; tt++) {
        const int bb = tt & 1;
        if (tt < NTILE - 1) {
            fill(t0 + tt + 1, bb ^ 1);
            asm volatile("cp.async.wait_group 1;" ::: "memory");
        } else {
            asm volatile("cp.async.wait_group 0;" ::: "memory");
        }
        __syncthreads();

        const float* ksS = dyn + bb * ABUF;
        const float* vtS = ksS + AOFF_VT;
        const float* krf = ksS + AOFF_KR;
        const float* kcf = ksS + AOFF_KC;

#pragma unroll
        for (int gr = 0; gr < 16; gr++) {
            const float* krow = ksS + (gr * 8 + sg) * KS_F;
            uint32_t kb0[4], kb1[4];
#pragma unroll
            for (int s = 0; s < 4; s++) {
                kb0[s] = __float_as_uint(krow[s * 8 + t4]);
                kb1[s] = __float_as_uint(krow[s * 8 + t4 + 4]);
            }
            float sf[2][4];
#pragma unroll
            for (int mi = 0; mi < 2; mi++) {
                sf[mi][0] = sf[mi][1] = sf[mi][2] = sf[mi][3] = 0.f;
#pragma unroll
                for (int s = 0; s < 4; s++)
                    mma_tf32(sf[mi], qA[mi][s], kb0[s], kb1[s], sf[mi]);
            }
            int col0 = gr * 8 + t4;
            int col1 = col0 + 4;
            float kra = krf[col0], kca = kcf[col0];
            float krb = krf[col1], kcb = kcf[col1];

            uint32_t aP[2][4];
#pragma unroll
            for (int mi = 0; mi < 2; mi++) {
                float p0 = to_tf32f(__expf(fmaf(decay,
                    fabsf(qrF[mi][0] - kra) + fabsf(qcF[mi][0] - kca), sf[mi][0])));
                float p1 = to_tf32f(__expf(fmaf(decay,
                    fabsf(qrF[mi][0] - krb) + fabsf(qcF[mi][0] - kcb), sf[mi][1])));
                float p2 = to_tf32f(__expf(fmaf(decay,
                    fabsf(qrF[mi][1] - kra) + fabsf(qcF[mi][1] - kca), sf[mi][2])));
                float p3 = to_tf32f(__expf(fmaf(decay,
                    fabsf(qrF[mi][1] - krb) + fabsf(qcF[mi][1] - kcb), sf[mi][3])));
                lA[mi] += p0 + p1;
                lB[mi] += p2 + p3;
                aP[mi][0] = __float_as_uint(p0);
                aP[mi][1] = __float_as_uint(p2);
                aP[mi][2] = __float_as_uint(p1);
                aP[mi][3] = __float_as_uint(p3);
            }

#pragma unroll
            for (int nc = 0; nc < 4; nc++) {
                const float* vrow = vtS + (nc * 8 + grp) * VT_F + gr * 8;
                uint32_t b0 = __float_as_uint(vrow[t4]);
                uint32_t b1 = __float_as_uint(vrow[t4 + 4]);
#pragma unroll
                for (int mi = 0; mi < 2; mi++)
                    mma_tf32(o[mi][nc], aP[mi], b0, b1, o[mi][nc]);
            }
        }
        __syncthreads();
    }

#pragma unroll
    for (int mi = 0; mi < 2; mi++) {
        lA[mi] += __shfl_xor_sync(0xFFFFFFFFu, lA[mi], 1);
        lA[mi] += __shfl_xor_sync(0xFFFFFFFFu, lA[mi], 2);
        lB[mi] += __shfl_xor_sync(0xFFFFFFFFu, lB[mi], 1);
        lB[mi] += __shfl_xor_sync(0xFFFFFFFFu, lB[mi], 2);
    }

    // store unnormalized partials
    float* pbase = g_part + (((size_t)(half * BH + bh)) * NPOS) * HD;
#pragma unroll
    for (int mi = 0; mi < 2; mi++) {
        const int r0 = rowA + mi * 16;
        float* p0 = pbase + (size_t)r0 * HD;
        float* p8 = pbase + (size_t)(r0 + 8) * HD;
#pragma unroll
        for (int nc = 0; nc < 4; nc++) {
            int d = nc * 8 + t4 * 2;
            *(float2*)(p0 + d) = make_float2(o[mi][nc][0], o[mi][nc][1]);
            *(float2*)(p8 + d) = make_float2(o[mi][nc][2], o[mi][nc][3]);
        }
        if (t4 == 0) {
            g_partl[(half * BH + bh) * NPOS + r0] = lA[mi];
            g_partl[(half * BH + bh) * NPOS + r0 + 8] = lB[mi];
        }
    }
}

// ---------------------------------------------------------------------------
// tf32-mma output GEMM with fused split-K merge:
// out = ((O0+O1)/(l0+l1) + lepe) @ Wo + bo
// A-tile built directly from g_part/g_partl/g_lepe. grid (MTOT/128, CDIM/64)
// ---------------------------------------------------------------------------
__global__ __launch_bounds__(128) void out_mma(
    const float* __restrict__ Wo, const float* __restrict__ bo,
    float* __restrict__ out)
{
    __shared__ __align__(16) float xs[128 * XS];
    __shared__ __align__(16) float ws[32 * WS];

    const int tid = threadIdx.x;
    const int lane = tid & 31, wid = tid >> 5;
    const int grp = lane >> 2, t4 = lane & 3;
    const int mb = blockIdx.x * 128, nb = blockIdx.y * 64;

    float acc[2][8][4];
#pragma unroll
    for (int mi = 0; mi < 2; mi++)
#pragma unroll
        for (int n = 0; n < 8; n++)
#pragma unroll
            for (int j = 0; j < 4; j++) acc[mi][n][j] = 0.f;

    for (int k0 = 0; k0 < CDIM; k0 += 32) {
        const int head = k0 >> 5;     // all cols in this chunk belong to one head
        __syncthreads();
#pragma unroll
        for (int i = 0; i < 8; i++) {
            int idx = tid + i * 128;
            int row = idx >> 3, c = idx & 7;
            int R = mb + row;
            int b = (R >= NPOS) ? 1 : 0;
            int pos = R - b * NPOS;
            int bhh = b * HEADS + head;
            float l0 = g_partl[bhh * NPOS + pos];
            float l1 = g_partl[(BH + bhh) * NPOS + pos];
            float inv = 1.0f / (l0 + l1);
            float4 a0 = *(const float4*)(g_part + ((size_t)bhh * NPOS + pos) * HD + c * 4);
            float4 a1 = *(const float4*)(g_part + ((size_t)(BH + bhh) * NPOS + pos) * HD + c * 4);
            float4 e = *(const float4*)&g_lepe[(size_t)R * CDIM + k0 + c * 4];
            float4 r;
            r.x = to_tf32f((a0.x + a1.x) * inv + e.x);
            r.y = to_tf32f((a0.y + a1.y) * inv + e.y);
            r.z = to_tf32f((a0.z + a1.z) * inv + e.z);
            r.w = to_tf32f((a0.w + a1.w) * inv + e.w);
            *(float4*)(xs + row * XS + c * 4) = r;
        }
#pragma unroll
        for (int i = 0; i < 4; i++) {
            int idx = tid + i * 128;
            int row = idx >> 4, c = idx & 15;
            float4 a = *(const float4*)&Wo[(size_t)(k0 + row) * CDIM + nb + c * 4];
            a.x = to_tf32f(a.x); a.y = to_tf32f(a.y);
            a.z = to_tf32f(a.z); a.w = to_tf32f(a.w);
            *(float4*)(ws + row * WS + c * 4) = a;
        }
        __syncthreads();

#pragma unroll
        for (int ks = 0; ks < 4; ks++) {
            uint32_t bf[8][2];
#pragma unroll
            for (int n = 0; n < 8; n++) {
                bf[n][0] = __float_as_uint(ws[(ks * 8 + t4) * WS + n * 8 + grp]);
                bf[n][1] = __float_as_uint(ws[(ks * 8 + t4 + 4) * WS + n * 8 + grp]);
            }
            uint32_t af[2][4];
#pragma unroll
            for (int mi = 0; mi < 2; mi++) {
                const float* xrow = xs + (wid * 32 + mi * 16 + grp) * XS + ks * 8;
                const float* xrow8 = xrow + 8 * XS;
                af[mi][0] = __float_as_uint(xrow[t4]);
                af[mi][1] = __float_as_uint(xrow8[t4]);
                af[mi][2] = __float_as_uint(xrow[t4 + 4]);
                af[mi][3] = __float_as_uint(xrow8[t4 + 4]);
            }
#pragma unroll
            for (int mi = 0; mi < 2; mi++)
#pragma unroll
                for (int n = 0; n < 8; n++)
                    mma_tf32(acc[mi][n], af[mi], bf[n][0], bf[n][1], acc[mi][n]);
        }
    }

#pragma unroll
    for (int mi = 0; mi < 2; mi++) {
#pragma unroll
        for (int rh = 0; rh < 2; rh++) {
            int row = mb + wid * 32 + mi * 16 + rh * 8 + grp;
#pragma unroll
            for (int n = 0; n < 8; n++) {
                int col = nb + n * 8 + 2 * t4;
                float v0 = acc[mi][n][rh * 2 + 0] + bo[col];
                float v1 = acc[mi][n][rh * 2 + 1] + bo[col + 1];
                *(float2*)&out[(size_t)row * CDIM + col] = make_float2(v0, v1);
            }
        }
    }
}

// ---------------------------------------------------------------------------
extern "C" void kernel_launch(void* const* d_in, const int* in_sizes, int n_in,
                              void* d_out, int out_size)
{
    const float* x      = (const float*)d_in[0];
    const float* Wq     = (const float*)d_in[1];
    const float* bq     = (const float*)d_in[2];
    const float* Wk     = (const float*)d_in[3];
    const float* bk     = (const float*)d_in[4];
    const float* Wv     = (const float*)d_in[5];
    const float* bv     = (const float*)d_in[6];
    const float* lepe_w = (const float*)d_in[7];
    const float* lepe_b = (const float*)d_in[8];
    const float* Wo     = (const float*)d_in[9];
    const float* bo     = (const float*)d_in[10];
    float* out = (float*)d_out;

    setup_tables<<<(NPOS * 16 + 25 * CDIM + 255) / 256, 256>>>(lepe_w);

    dim3 g1(MTOT / 128, CDIM / 64, 3);
    qkv_mma<<<g1, 128>>>(x, Wq, bq, Wk, bk, Wv, bv);

    dim3 gv(NPOS / 32, BH);
    vt_kernel<<<gv, dim3(32, 8)>>>();

    dwconv<<<(MTOT * CDIM / 4) / 256, 256>>>(lepe_b);

    const int attn_smem = 2 * ABUF * 4;   // 72704 B
    cudaFuncSetAttribute(attn_pipe, cudaFuncAttributeMaxDynamicSharedMemorySize, attn_smem);
    dim3 g3(NPOS / 256, BH, 2);
    attn_pipe<<<g3, 256, attn_smem>>>();

    dim3 g4(MTOT / 128, CDIM / 64);
    out_mma<<<g4, 128>>>(Wo, bo, out);
}